// round 12
// baseline (speedup 1.0000x reference)
#include <cuda_runtime.h>
#include <cuda_fp16.h>
#include <cstdint>
#include <math.h>

// ---------------------------------------------------------------------------
// Problem constants: B=2, Lq=21760, C=256, FD=1024, NH=8, d=32, NL=4, NP=4
// ---------------------------------------------------------------------------
#define MROWS 43520
#define CDIM  256
#define FDIM  1024

// Scratch (device globals)
__device__ float  g_q    [MROWS * CDIM];   // rounded q
__device__ float  g_srcr [MROWS * CDIM];   // rounded src
__device__ __half g_val  [MROWS * CDIM];   // value projection (half — L2 gather traffic)
__device__ float  g_off  [MROWS * CDIM];
__device__ float  g_aw   [MROWS * 128];    // logits (softmax fused into sampler)
__device__ float  g_attn [MROWS * CDIM];   // rounded
__device__ float  g_x    [MROWS * CDIM];
__device__ float  g_xr   [MROWS * CDIM];   // rounded
__device__ float  g_hid  [MROWS * FDIM];   // rounded
__device__ float  g_f    [MROWS * CDIM];
__device__ float  g_wt   [3 * 65536 + 32768 + 2 * 262144]; // rounded, [N][K]

#define WT_WV   0
#define WT_WOFF 65536
#define WT_WAW  131072
#define WT_WO   163840
#define WT_W1   229376
#define WT_W2   491520

// ---------------------------------------------------------------------------
// helpers
// ---------------------------------------------------------------------------
__device__ __forceinline__ uint32_t f2tf32(float v) {
    uint32_t o;
    asm("cvt.rna.tf32.f32 %0, %1;" : "=r"(o) : "f"(v));
    return o;
}
__device__ __forceinline__ float rtf(float v) { return __uint_as_float(f2tf32(v)); }

__device__ __forceinline__ void mma_tf32(float* d, const uint32_t* a, uint32_t b0, uint32_t b1) {
    asm volatile(
        "mma.sync.aligned.m16n8k8.row.col.f32.tf32.tf32.f32 "
        "{%0,%1,%2,%3}, {%4,%5,%6,%7}, {%8,%9}, {%0,%1,%2,%3};"
        : "+f"(d[0]), "+f"(d[1]), "+f"(d[2]), "+f"(d[3])
        : "r"(a[0]), "r"(a[1]), "r"(a[2]), "r"(a[3]), "r"(b0), "r"(b1));
}

__device__ __forceinline__ void ldsm4(uint32_t& r0, uint32_t& r1, uint32_t& r2, uint32_t& r3,
                                      uint32_t addr) {
    asm volatile("ldmatrix.sync.aligned.m8n8.x4.shared.b16 {%0,%1,%2,%3}, [%4];"
                 : "=r"(r0), "=r"(r1), "=r"(r2), "=r"(r3) : "r"(addr));
}

__device__ __forceinline__ uint32_t smem_u32(const void* p) {
    uint32_t a;
    asm("{ .reg .u64 t; cvta.to.shared.u64 t, %1; cvt.u32.u64 %0, t; }" : "=r"(a) : "l"(p));
    return a;
}
__device__ __forceinline__ void cp16(uint32_t dst, const void* src) {
    asm volatile("cp.async.ca.shared.global [%0], [%1], 16;" :: "r"(dst), "l"(src));
}
#define CP_COMMIT() asm volatile("cp.async.commit_group;" ::: "memory")
#define CP_WAIT1()  asm volatile("cp.async.wait_group 1;" ::: "memory")
#define CP_WAIT0()  asm volatile("cp.async.wait_group 0;" ::: "memory")

// ---------------------------------------------------------------------------
// Weight transpose + tf32 round: Wt[n*K+k] = round(W[k*N+n])
// ---------------------------------------------------------------------------
__global__ void transpose_kernel(const float* __restrict__ W, float* __restrict__ Wt, int K, int N) {
    __shared__ float t[32][33];
    const int n0 = blockIdx.x * 32, k0 = blockIdx.y * 32;
    const int tx = threadIdx.x, ty = threadIdx.y;
    for (int r = ty; r < 32; r += 8) t[r][tx] = W[(long)(k0 + r) * N + n0 + tx];
    __syncthreads();
    for (int r = ty; r < 32; r += 8) Wt[(long)(n0 + r) * K + k0 + tx] = rtf(t[tx][r]);
}

// ---------------------------------------------------------------------------
// Tensor-core tf32 GEMM: C[M,N] = A[M,K] @ Bt[N,K]^T + bias.
// BM=BN=128, BK=32, 128 threads (4 warps, 2x2), warp tile 64x64.
// cp.async 2-stage pipeline + ldmatrix fragment loads.
// Smem pitch 36 u32 -> conflict-free LDSM row fetches.
// Requires M%128==0, N%128==0, K%32==0. Inputs pre-rounded to tf32.
// HOUT: store output as __half (for the value projection feeding the sampler).
// ---------------------------------------------------------------------------
#define GP 36
#define AMAT 4608              // 128*36 u32 per matrix
#define STAGE_U32 (2 * AMAT)   // A + B per stage
#define GSMEM_BYTES (2 * STAGE_U32 * 4)  // 73728

template <bool RELU, bool ROUND, bool HOUT>
__global__ __launch_bounds__(128, 2)
void gemm_mma_kernel(const float* __restrict__ A, const float* __restrict__ Bt,
                     const float* __restrict__ bias, void* __restrict__ Cv,
                     int M, int N, int K) {
    extern __shared__ uint32_t sm[];

    const int tid = threadIdx.x;
    const int wid = tid >> 5;
    const int lid = tid & 31;
    const int row0 = blockIdx.y * 128;
    const int col0 = blockIdx.x * 128;
    const int wm = (wid & 1) * 64;
    const int wn = (wid >> 1) * 64;
    const int r = lid >> 2;          // 0..7
    const int c = lid & 3;           // 0..3

    // copy geometry: 8 slots/matrix, slot s -> row rbase+16s, fixed kq
    const int rbase = tid >> 3;          // 0..15
    const int kq    = (tid & 7) * 4;     // 0..28
    const float* Ag = A  + (long)(row0 + rbase) * K + kq;
    const float* Bg = Bt + (long)(col0 + rbase) * K + kq;
    const uint32_t smBase = smem_u32(sm);

    // ldmatrix per-lane word offsets (within stage)
    uint32_t aoff[4];
#pragma unroll
    for (int mt = 0; mt < 4; mt++)
        aoff[mt] = (uint32_t)((wm + mt * 16 + (lid & 15)) * GP + 4 * (lid >> 4));
    uint32_t boff[4];
#pragma unroll
    for (int p = 0; p < 4; p++)
        boff[p] = (uint32_t)(AMAT + (wn + p * 16 + (lid & 7) + 8 * (lid >> 4)) * GP
                             + 4 * ((lid >> 3) & 1));

    const int nk = K >> 5;

    float acc[4][8][4];
#pragma unroll
    for (int mt = 0; mt < 4; mt++)
#pragma unroll
        for (int nt = 0; nt < 8; nt++)
#pragma unroll
            for (int e = 0; e < 4; e++) acc[mt][nt][e] = 0.f;

    // prologue: stage 0, chunk 0
    {
        const uint32_t sA = smBase;
        const uint32_t sB = smBase + AMAT * 4;
#pragma unroll
        for (int s = 0; s < 8; s++) {
            const int row = rbase + 16 * s;
            const uint32_t so = (uint32_t)(row * GP + kq) * 4;
            cp16(sA + so, Ag + (long)(16 * s) * K);
            cp16(sB + so, Bg + (long)(16 * s) * K);
        }
        CP_COMMIT();
    }

    for (int i = 0; i < nk; i++) {
        const int cur = i & 1;
        if (i + 1 < nk) {
            const int nxt = cur ^ 1;
            const uint32_t sA = smBase + (uint32_t)nxt * STAGE_U32 * 4;
            const uint32_t sB = sA + AMAT * 4;
            const long ko = (long)(i + 1) * 32;
#pragma unroll
            for (int s = 0; s < 8; s++) {
                const int row = rbase + 16 * s;
                const uint32_t so = (uint32_t)(row * GP + kq) * 4;
                cp16(sA + so, Ag + (long)(16 * s) * K + ko);
                cp16(sB + so, Bg + (long)(16 * s) * K + ko);
            }
            CP_COMMIT();
            CP_WAIT1();
        } else {
            CP_WAIT0();
        }
        __syncthreads();

        const uint32_t stageB = smBase + (uint32_t)cur * STAGE_U32 * 4;

#pragma unroll
        for (int ks = 0; ks < 4; ks++) {
            const uint32_t kb4 = (uint32_t)(ks * 8) * 4;
            uint32_t a[4][4];
#pragma unroll
            for (int mt = 0; mt < 4; mt++)
                ldsm4(a[mt][0], a[mt][1], a[mt][2], a[mt][3], stageB + aoff[mt] * 4 + kb4);
            uint32_t b[8][2];
#pragma unroll
            for (int p = 0; p < 4; p++)
                ldsm4(b[2 * p][0], b[2 * p][1], b[2 * p + 1][0], b[2 * p + 1][1],
                      stageB + boff[p] * 4 + kb4);
#pragma unroll
            for (int nt = 0; nt < 8; nt++)
#pragma unroll
                for (int mt = 0; mt < 4; mt++)
                    mma_tf32(acc[mt][nt], a[mt], b[nt][0], b[nt][1]);
        }
        __syncthreads();
    }

    // epilogue
    float2 bias2[8];
#pragma unroll
    for (int nt = 0; nt < 8; nt++)
        bias2[nt] = *(const float2*)&bias[col0 + wn + nt * 8 + 2 * c];

#pragma unroll
    for (int mt = 0; mt < 4; mt++) {
        const long gr0 = row0 + wm + mt * 16 + r;
        const long gr1 = gr0 + 8;
#pragma unroll
        for (int nt = 0; nt < 8; nt++) {
            const int gc = col0 + wn + nt * 8 + 2 * c;
            float2 v0, v1;
            v0.x = acc[mt][nt][0] + bias2[nt].x;
            v0.y = acc[mt][nt][1] + bias2[nt].y;
            v1.x = acc[mt][nt][2] + bias2[nt].x;
            v1.y = acc[mt][nt][3] + bias2[nt].y;
            if (RELU) {
                v0.x = fmaxf(v0.x, 0.f); v0.y = fmaxf(v0.y, 0.f);
                v1.x = fmaxf(v1.x, 0.f); v1.y = fmaxf(v1.y, 0.f);
            }
            if (ROUND) {
                v0.x = rtf(v0.x); v0.y = rtf(v0.y);
                v1.x = rtf(v1.x); v1.y = rtf(v1.y);
            }
            if (HOUT) {
                __half* C = (__half*)Cv;
                *(__half2*)&C[gr0 * N + gc] = __floats2half2_rn(v0.x, v0.y);
                *(__half2*)&C[gr1 * N + gc] = __floats2half2_rn(v1.x, v1.y);
            } else {
                float* C = (float*)Cv;
                *(float2*)&C[gr0 * N + gc] = v0;
                *(float2*)&C[gr1 * N + gc] = v1;
            }
        }
    }
}

// ---------------------------------------------------------------------------
// q = round(src + pos); src_r = round(src)
// ---------------------------------------------------------------------------
__global__ void addq_kernel(const float* __restrict__ a, const float* __restrict__ b,
                            float* __restrict__ q, float* __restrict__ sr, int n) {
    int i = blockIdx.x * blockDim.x + threadIdx.x;
    if (i < n) {
        float s = a[i];
        q[i] = rtf(s + b[i]);
        sr[i] = rtf(s);
    }
}

// ---------------------------------------------------------------------------
// Deformable sampling with fused softmax (input = logits; value half).
// One block per token (256 threads = 8 heads x 32 ch).
// ---------------------------------------------------------------------------
__global__ void sample_kernel(const __half* __restrict__ value, const float* __restrict__ off,
                              const float* __restrict__ awl, const float* __restrict__ refp,
                              const int* __restrict__ shapes, const int* __restrict__ lstart,
                              float* __restrict__ outp, int Lq) {
    const int row = blockIdx.x;
    const int t = threadIdx.x;
    const int b = row / Lq;

    __shared__ float s_off[256];
    __shared__ float s_aw[128];
    __shared__ float s_ref[8];
    __shared__ int   s_hw[8];
    __shared__ int   s_st[4];

    s_off[t] = off[row * 256 + t];
    if (t < 8)   s_ref[t] = refp[row * 8 + t];
    if (t < 8)   s_hw[t] = shapes[t];
    if (t < 4)   s_st[t] = lstart[t];
    if (t < 128) {
        const float v = awl[row * 128 + t];
        float m = v;
#pragma unroll
        for (int o = 8; o > 0; o >>= 1) m = fmaxf(m, __shfl_xor_sync(0xffffffffu, m, o, 16));
        const float e = expf(v - m);
        float s = e;
#pragma unroll
        for (int o = 8; o > 0; o >>= 1) s += __shfl_xor_sync(0xffffffffu, s, o, 16);
        s_aw[t] = e / s;
    }
    __syncthreads();

    const int h = t >> 5;
    const int j = t & 31;
    const int vbase = b * Lq * 256 + h * 32 + j;

    float acc = 0.f;
#pragma unroll
    for (int l = 0; l < 4; l++) {
        const int Hl = s_hw[l * 2], Wl = s_hw[l * 2 + 1];
        const int st = s_st[l];
        const float rx = s_ref[l * 2], ry = s_ref[l * 2 + 1];
        const float fW = (float)Wl, fH = (float)Hl;
#pragma unroll
        for (int p = 0; p < 4; p++) {
            const int oi = (h * 16 + l * 4 + p) * 2;
            const float px = (rx + s_off[oi] / fW) * fW - 0.5f;
            const float py = (ry + s_off[oi + 1] / fH) * fH - 0.5f;
            const float fx = floorf(px), fy = floorf(py);
            const int x0 = (int)fx, y0 = (int)fy;
            const float wx1 = px - fx, wy1 = py - fy;
            const float wx0 = 1.f - wx1, wy0 = 1.f - wy1;
            const float a = s_aw[h * 16 + l * 4 + p];

#pragma unroll
            for (int dy = 0; dy < 2; dy++) {
                const int yi = y0 + dy;
                if (yi < 0 || yi >= Hl) continue;
                const float wy = dy ? wy1 : wy0;
#pragma unroll
                for (int dx = 0; dx < 2; dx++) {
                    const int xi = x0 + dx;
                    if (xi < 0 || xi >= Wl) continue;
                    const float wx = dx ? wx1 : wx0;
                    acc += a * wx * wy *
                           __half2float(value[vbase + (st + yi * Wl + xi) * 256]);
                }
            }
        }
    }
    outp[row * 256 + t] = rtf(acc);
}

// ---------------------------------------------------------------------------
// LayerNorm over C=256 of (A + B); optional rounded side copy
// ---------------------------------------------------------------------------
__global__ void ln_kernel(const float* __restrict__ A, const float* __restrict__ Bt,
                          const float* __restrict__ g, const float* __restrict__ be,
                          float* __restrict__ out, float* __restrict__ out_r) {
    const int row = blockIdx.x;
    const int t = threadIdx.x;
    const float v = A[row * 256 + t] + Bt[row * 256 + t];

    __shared__ float sh[8];
    __shared__ float sh2[8];

    float s = v;
#pragma unroll
    for (int o = 16; o > 0; o >>= 1) s += __shfl_xor_sync(0xffffffffu, s, o);
    if ((t & 31) == 0) sh[t >> 5] = s;
    __syncthreads();
    float mean = 0.f;
#pragma unroll
    for (int i = 0; i < 8; i++) mean += sh[i];
    mean *= (1.f / 256.f);

    const float d = v - mean;
    float s2 = d * d;
#pragma unroll
    for (int o = 16; o > 0; o >>= 1) s2 += __shfl_xor_sync(0xffffffffu, s2, o);
    if ((t & 31) == 0) sh2[t >> 5] = s2;
    __syncthreads();
    float var = 0.f;
#pragma unroll
    for (int i = 0; i < 8; i++) var += sh2[i];
    var *= (1.f / 256.f);

    const float o = d * rsqrtf(var + 1e-5f) * g[t] + be[t];
    out[row * 256 + t] = o;
    if (out_r) out_r[row * 256 + t] = rtf(o);
}

// ---------------------------------------------------------------------------
// Launch
// ---------------------------------------------------------------------------
extern "C" void kernel_launch(void* const* d_in, const int* in_sizes, int n_in,
                              void* d_out, int out_size) {
    const float* src  = (const float*)d_in[0];
    const float* pos  = (const float*)d_in[1];
    const float* refp = (const float*)d_in[2];
    const int*   shp  = (const int*)d_in[3];
    const int*   lst  = (const int*)d_in[4];
    const float* Wv   = (const float*)d_in[5];
    const float* bv   = (const float*)d_in[6];
    const float* Woff = (const float*)d_in[7];
    const float* boff = (const float*)d_in[8];
    const float* Waw  = (const float*)d_in[9];
    const float* baw  = (const float*)d_in[10];
    const float* Wo   = (const float*)d_in[11];
    const float* bo   = (const float*)d_in[12];
    const float* W1   = (const float*)d_in[13];
    const float* b1   = (const float*)d_in[14];
    const float* W2   = (const float*)d_in[15];
    const float* b2   = (const float*)d_in[16];
    const float* g1   = (const float*)d_in[17];
    const float* be1  = (const float*)d_in[18];
    const float* g2   = (const float*)d_in[19];
    const float* be2  = (const float*)d_in[20];

    const int M = in_sizes[0] / CDIM;   // 43520
    const int Lq = 21760;
    float* out = (float*)d_out;

    float *q, *srcr, *off, *aw, *attn, *x, *xr, *hid, *f, *wt;
    __half *val;
    cudaGetSymbolAddress((void**)&q,    g_q);
    cudaGetSymbolAddress((void**)&srcr, g_srcr);
    cudaGetSymbolAddress((void**)&val,  g_val);
    cudaGetSymbolAddress((void**)&off,  g_off);
    cudaGetSymbolAddress((void**)&aw,   g_aw);
    cudaGetSymbolAddress((void**)&attn, g_attn);
    cudaGetSymbolAddress((void**)&x,    g_x);
    cudaGetSymbolAddress((void**)&xr,   g_xr);
    cudaGetSymbolAddress((void**)&hid,  g_hid);
    cudaGetSymbolAddress((void**)&f,    g_f);
    cudaGetSymbolAddress((void**)&wt,   g_wt);

    cudaFuncSetAttribute(gemm_mma_kernel<false, false, false>,
                         cudaFuncAttributeMaxDynamicSharedMemorySize, GSMEM_BYTES);
    cudaFuncSetAttribute(gemm_mma_kernel<false, false, true>,
                         cudaFuncAttributeMaxDynamicSharedMemorySize, GSMEM_BYTES);
    cudaFuncSetAttribute(gemm_mma_kernel<true, true, false>,
                         cudaFuncAttributeMaxDynamicSharedMemorySize, GSMEM_BYTES);

    // transpose + round weights to [N][K]
    dim3 tb(32, 8);
    transpose_kernel<<<dim3(CDIM / 32, CDIM / 32), tb>>>(Wv,   wt + WT_WV,   CDIM, CDIM);
    transpose_kernel<<<dim3(CDIM / 32, CDIM / 32), tb>>>(Woff, wt + WT_WOFF, CDIM, CDIM);
    transpose_kernel<<<dim3(128 / 32,  CDIM / 32), tb>>>(Waw,  wt + WT_WAW,  CDIM, 128);
    transpose_kernel<<<dim3(CDIM / 32, CDIM / 32), tb>>>(Wo,   wt + WT_WO,   CDIM, CDIM);
    transpose_kernel<<<dim3(FDIM / 32, CDIM / 32), tb>>>(W1,   wt + WT_W1,   CDIM, FDIM);
    transpose_kernel<<<dim3(CDIM / 32, FDIM / 32), tb>>>(W2,   wt + WT_W2,   FDIM, CDIM);

    const int nElem = M * CDIM;
    addq_kernel<<<(nElem + 255) / 256, 256>>>(src, pos, q, srcr, nElem);

    dim3 blk(128);
    // val (HALF out) = src_r @ Wv + bv
    gemm_mma_kernel<false, false, true><<<dim3(CDIM / 128, M / 128), blk, GSMEM_BYTES>>>(
        srcr, wt + WT_WV, bv, val, M, CDIM, CDIM);
    // off = q @ Woff + boff
    gemm_mma_kernel<false, false, false><<<dim3(CDIM / 128, M / 128), blk, GSMEM_BYTES>>>(
        q, wt + WT_WOFF, boff, off, M, CDIM, CDIM);
    // aw logits = q @ Waw + baw
    gemm_mma_kernel<false, false, false><<<dim3(1, M / 128), blk, GSMEM_BYTES>>>(
        q, wt + WT_WAW, baw, aw, M, 128, CDIM);
    // sampling (softmax fused), half value gathers, rounded fp32 out
    sample_kernel<<<M, 256>>>(val, off, aw, refp, shp, lst, attn, Lq);
    // f = attn @ Wo + bo
    gemm_mma_kernel<false, false, false><<<dim3(CDIM / 128, M / 128), blk, GSMEM_BYTES>>>(
        attn, wt + WT_WO, bo, f, M, CDIM, CDIM);
    ln_kernel<<<M, 256>>>(src, f, g1, be1, x, xr);
    // hid (rounded, relu) = xr @ W1 + b1
    gemm_mma_kernel<true, true, false><<<dim3(FDIM / 128, M / 128), blk, GSMEM_BYTES>>>(
        xr, wt + WT_W1, b1, hid, M, FDIM, CDIM);
    // f = hid @ W2 + b2
    gemm_mma_kernel<false, false, false><<<dim3(CDIM / 128, M / 128), blk, GSMEM_BYTES>>>(
        hid, wt + WT_W2, b2, f, M, CDIM, FDIM);
    ln_kernel<<<M, 256>>>(x, f, g2, be2, out, nullptr);
}

// round 14
// speedup vs baseline: 1.5660x; 1.5660x over previous
#include <cuda_runtime.h>
#include <cstdint>
#include <math.h>

// ---------------------------------------------------------------------------
// Problem constants: B=2, Lq=21760, C=256, FD=1024, NH=8, d=32, NL=4, NP=4
// ---------------------------------------------------------------------------
#define MROWS 43520
#define CDIM  256
#define FDIM  1024

// Scratch (device globals)
__device__ float g_q    [MROWS * CDIM];   // rounded q
__device__ float g_srcr [MROWS * CDIM];   // rounded src
__device__ float g_val  [MROWS * CDIM];
__device__ float g_offaw[MROWS * 384];    // cols 0..255 offsets, 256..383 aw logits
__device__ float g_attn [MROWS * CDIM];   // rounded
__device__ float g_x    [MROWS * CDIM];
__device__ float g_xr   [MROWS * CDIM];   // rounded
__device__ float g_hid  [MROWS * FDIM];   // rounded
__device__ float g_f    [MROWS * CDIM];
__device__ float g_wt   [3 * 65536 + 32768 + 2 * 262144]; // rounded, [N][K]
__device__ float g_bcat [384];            // boff ++ baw

#define WT_WV   0
#define WT_WOFF 65536            // [384][256] combined: Woff rows 0..255, Waw rows 256..383
#define WT_WAW  131072
#define WT_WO   163840
#define WT_W1   229376
#define WT_W2   491520

// ---------------------------------------------------------------------------
// helpers
// ---------------------------------------------------------------------------
__device__ __forceinline__ uint32_t f2tf32(float v) {
    uint32_t o;
    asm("cvt.rna.tf32.f32 %0, %1;" : "=r"(o) : "f"(v));
    return o;
}
__device__ __forceinline__ float rtf(float v) { return __uint_as_float(f2tf32(v)); }

__device__ __forceinline__ void mma_tf32(float* d, const uint32_t* a, uint32_t b0, uint32_t b1) {
    asm volatile(
        "mma.sync.aligned.m16n8k8.row.col.f32.tf32.tf32.f32 "
        "{%0,%1,%2,%3}, {%4,%5,%6,%7}, {%8,%9}, {%0,%1,%2,%3};"
        : "+f"(d[0]), "+f"(d[1]), "+f"(d[2]), "+f"(d[3])
        : "r"(a[0]), "r"(a[1]), "r"(a[2]), "r"(a[3]), "r"(b0), "r"(b1));
}

__device__ __forceinline__ void ldsm4(uint32_t& r0, uint32_t& r1, uint32_t& r2, uint32_t& r3,
                                      uint32_t addr) {
    asm volatile("ldmatrix.sync.aligned.m8n8.x4.shared.b16 {%0,%1,%2,%3}, [%4];"
                 : "=r"(r0), "=r"(r1), "=r"(r2), "=r"(r3) : "r"(addr));
}

__device__ __forceinline__ uint32_t smem_u32(const void* p) {
    uint32_t a;
    asm("{ .reg .u64 t; cvta.to.shared.u64 t, %1; cvt.u32.u64 %0, t; }" : "=r"(a) : "l"(p));
    return a;
}
__device__ __forceinline__ void cp16(uint32_t dst, const void* src) {
    asm volatile("cp.async.ca.shared.global [%0], [%1], 16;" :: "r"(dst), "l"(src));
}
#define CP_COMMIT() asm volatile("cp.async.commit_group;" ::: "memory")
#define CP_WAIT1()  asm volatile("cp.async.wait_group 1;" ::: "memory")
#define CP_WAIT0()  asm volatile("cp.async.wait_group 0;" ::: "memory")

// ---------------------------------------------------------------------------
// Weight transpose + tf32 round: Wt[n*K+k] = round(W[k*N+n])
// ---------------------------------------------------------------------------
__global__ void transpose_kernel(const float* __restrict__ W, float* __restrict__ Wt, int K, int N) {
    __shared__ float t[32][33];
    const int n0 = blockIdx.x * 32, k0 = blockIdx.y * 32;
    const int tx = threadIdx.x, ty = threadIdx.y;
    for (int r = ty; r < 32; r += 8) t[r][tx] = W[(long)(k0 + r) * N + n0 + tx];
    __syncthreads();
    for (int r = ty; r < 32; r += 8) Wt[(long)(n0 + r) * K + k0 + tx] = rtf(t[tx][r]);
}

// concat biases: bcat = [boff(256), baw(128)]
__global__ void bcat_kernel(const float* __restrict__ boff, const float* __restrict__ baw,
                            float* __restrict__ bcat) {
    int i = threadIdx.x + blockIdx.x * blockDim.x;
    if (i < 256) bcat[i] = boff[i];
    else if (i < 384) bcat[i] = baw[i - 256];
}

// ---------------------------------------------------------------------------
// Tensor-core tf32 GEMM: C[M,N] = A[M,K] @ Bt[N,K]^T + bias.
// BM=BN=128, BK=32, 128 threads (4 warps, 2x2), warp tile 64x64.
// cp.async 2-stage pipeline + ldmatrix fragment loads.
// Smem pitch 36 u32 -> conflict-free LDSM row fetches.
// Requires M%128==0, N%128==0, K%32==0. Inputs pre-rounded to tf32.
// ---------------------------------------------------------------------------
#define GP 36
#define AMAT 4608              // 128*36 u32 per matrix
#define STAGE_U32 (2 * AMAT)   // A + B per stage
#define GSMEM_BYTES (2 * STAGE_U32 * 4)  // 73728

template <bool RELU, bool ROUND>
__global__ __launch_bounds__(128, 2)
void gemm_mma_kernel(const float* __restrict__ A, const float* __restrict__ Bt,
                     const float* __restrict__ bias, float* __restrict__ C,
                     int M, int N, int K) {
    extern __shared__ uint32_t sm[];

    const int tid = threadIdx.x;
    const int wid = tid >> 5;
    const int lid = tid & 31;
    const int row0 = blockIdx.y * 128;
    const int col0 = blockIdx.x * 128;
    const int wm = (wid & 1) * 64;
    const int wn = (wid >> 1) * 64;
    const int r = lid >> 2;          // 0..7
    const int c = lid & 3;           // 0..3

    // copy geometry: 8 slots/matrix, slot s -> row rbase+16s, fixed kq
    const int rbase = tid >> 3;          // 0..15
    const int kq    = (tid & 7) * 4;     // 0..28
    const float* Ag = A  + (long)(row0 + rbase) * K + kq;
    const float* Bg = Bt + (long)(col0 + rbase) * K + kq;
    const uint32_t smBase = smem_u32(sm);

    // ldmatrix per-lane word offsets (within stage)
    uint32_t aoff[4];
#pragma unroll
    for (int mt = 0; mt < 4; mt++)
        aoff[mt] = (uint32_t)((wm + mt * 16 + (lid & 15)) * GP + 4 * (lid >> 4));
    uint32_t boff4[4];
#pragma unroll
    for (int p = 0; p < 4; p++)
        boff4[p] = (uint32_t)(AMAT + (wn + p * 16 + (lid & 7) + 8 * (lid >> 4)) * GP
                              + 4 * ((lid >> 3) & 1));

    const int nk = K >> 5;

    float acc[4][8][4];
#pragma unroll
    for (int mt = 0; mt < 4; mt++)
#pragma unroll
        for (int nt = 0; nt < 8; nt++)
#pragma unroll
            for (int e = 0; e < 4; e++) acc[mt][nt][e] = 0.f;

    // prologue: stage 0, chunk 0
    {
        const uint32_t sA = smBase;
        const uint32_t sB = smBase + AMAT * 4;
#pragma unroll
        for (int s = 0; s < 8; s++) {
            const int row = rbase + 16 * s;
            const uint32_t so = (uint32_t)(row * GP + kq) * 4;
            cp16(sA + so, Ag + (long)(16 * s) * K);
            cp16(sB + so, Bg + (long)(16 * s) * K);
        }
        CP_COMMIT();
    }

    for (int i = 0; i < nk; i++) {
        const int cur = i & 1;
        if (i + 1 < nk) {
            const int nxt = cur ^ 1;
            const uint32_t sA = smBase + (uint32_t)nxt * STAGE_U32 * 4;
            const uint32_t sB = sA + AMAT * 4;
            const long ko = (long)(i + 1) * 32;
#pragma unroll
            for (int s = 0; s < 8; s++) {
                const int row = rbase + 16 * s;
                const uint32_t so = (uint32_t)(row * GP + kq) * 4;
                cp16(sA + so, Ag + (long)(16 * s) * K + ko);
                cp16(sB + so, Bg + (long)(16 * s) * K + ko);
            }
            CP_COMMIT();
            CP_WAIT1();
        } else {
            CP_WAIT0();
        }
        __syncthreads();

        const uint32_t stageB = smBase + (uint32_t)cur * STAGE_U32 * 4;

#pragma unroll
        for (int ks = 0; ks < 4; ks++) {
            const uint32_t kb4 = (uint32_t)(ks * 8) * 4;
            uint32_t a[4][4];
#pragma unroll
            for (int mt = 0; mt < 4; mt++)
                ldsm4(a[mt][0], a[mt][1], a[mt][2], a[mt][3], stageB + aoff[mt] * 4 + kb4);
            uint32_t b[8][2];
#pragma unroll
            for (int p = 0; p < 4; p++)
                ldsm4(b[2 * p][0], b[2 * p][1], b[2 * p + 1][0], b[2 * p + 1][1],
                      stageB + boff4[p] * 4 + kb4);
#pragma unroll
            for (int nt = 0; nt < 8; nt++)
#pragma unroll
                for (int mt = 0; mt < 4; mt++)
                    mma_tf32(acc[mt][nt], a[mt], b[nt][0], b[nt][1]);
        }
        __syncthreads();
    }

    // epilogue
    float2 bias2[8];
#pragma unroll
    for (int nt = 0; nt < 8; nt++)
        bias2[nt] = *(const float2*)&bias[col0 + wn + nt * 8 + 2 * c];

#pragma unroll
    for (int mt = 0; mt < 4; mt++) {
        const long gr0 = row0 + wm + mt * 16 + r;
        const long gr1 = gr0 + 8;
#pragma unroll
        for (int nt = 0; nt < 8; nt++) {
            const int gc = col0 + wn + nt * 8 + 2 * c;
            float2 v0, v1;
            v0.x = acc[mt][nt][0] + bias2[nt].x;
            v0.y = acc[mt][nt][1] + bias2[nt].y;
            v1.x = acc[mt][nt][2] + bias2[nt].x;
            v1.y = acc[mt][nt][3] + bias2[nt].y;
            if (RELU) {
                v0.x = fmaxf(v0.x, 0.f); v0.y = fmaxf(v0.y, 0.f);
                v1.x = fmaxf(v1.x, 0.f); v1.y = fmaxf(v1.y, 0.f);
            }
            if (ROUND) {
                v0.x = rtf(v0.x); v0.y = rtf(v0.y);
                v1.x = rtf(v1.x); v1.y = rtf(v1.y);
            }
            *(float2*)&C[gr0 * N + gc] = v0;
            *(float2*)&C[gr1 * N + gc] = v1;
        }
    }
}

// ---------------------------------------------------------------------------
// q = round(src + pos); src_r = round(src)
// ---------------------------------------------------------------------------
__global__ void addq_kernel(const float* __restrict__ a, const float* __restrict__ b,
                            float* __restrict__ q, float* __restrict__ sr, int n) {
    int i = blockIdx.x * blockDim.x + threadIdx.x;
    if (i < n) {
        float s = a[i];
        q[i] = rtf(s + b[i]);
        sr[i] = rtf(s);
    }
}

// ---------------------------------------------------------------------------
// Deformable sampling with fused softmax.
// offaw: [M][384] — cols 0..255 offsets, 256..383 aw logits.
// One block per token (256 threads = 8 heads x 32 ch).
// ---------------------------------------------------------------------------
__global__ void sample_kernel(const float* __restrict__ value, const float* __restrict__ offaw,
                              const float* __restrict__ refp,
                              const int* __restrict__ shapes, const int* __restrict__ lstart,
                              float* __restrict__ outp, int Lq) {
    const int row = blockIdx.x;
    const int t = threadIdx.x;
    const int b = row / Lq;

    __shared__ float s_off[256];
    __shared__ float s_aw[128];
    __shared__ float s_ref[8];
    __shared__ int   s_hw[8];
    __shared__ int   s_st[4];

    s_off[t] = offaw[(long)row * 384 + t];
    if (t < 8)   s_ref[t] = refp[row * 8 + t];
    if (t < 8)   s_hw[t] = shapes[t];
    if (t < 4)   s_st[t] = lstart[t];
    if (t < 128) {
        const float v = offaw[(long)row * 384 + 256 + t];
        float m = v;
#pragma unroll
        for (int o = 8; o > 0; o >>= 1) m = fmaxf(m, __shfl_xor_sync(0xffffffffu, m, o, 16));
        const float e = expf(v - m);
        float s = e;
#pragma unroll
        for (int o = 8; o > 0; o >>= 1) s += __shfl_xor_sync(0xffffffffu, s, o, 16);
        s_aw[t] = e / s;
    }
    __syncthreads();

    const int h = t >> 5;
    const int j = t & 31;
    const int vbase = b * Lq * 256 + h * 32 + j;

    float acc = 0.f;
#pragma unroll
    for (int l = 0; l < 4; l++) {
        const int Hl = s_hw[l * 2], Wl = s_hw[l * 2 + 1];
        const int st = s_st[l];
        const float rx = s_ref[l * 2], ry = s_ref[l * 2 + 1];
        const float fW = (float)Wl, fH = (float)Hl;
#pragma unroll
        for (int p = 0; p < 4; p++) {
            const int oi = (h * 16 + l * 4 + p) * 2;
            const float px = (rx + s_off[oi] / fW) * fW - 0.5f;
            const float py = (ry + s_off[oi + 1] / fH) * fH - 0.5f;
            const float fx = floorf(px), fy = floorf(py);
            const int x0 = (int)fx, y0 = (int)fy;
            const float wx1 = px - fx, wy1 = py - fy;
            const float wx0 = 1.f - wx1, wy0 = 1.f - wy1;
            const float a = s_aw[h * 16 + l * 4 + p];

#pragma unroll
            for (int dy = 0; dy < 2; dy++) {
                const int yi = y0 + dy;
                if (yi < 0 || yi >= Hl) continue;
                const float wy = dy ? wy1 : wy0;
#pragma unroll
                for (int dx = 0; dx < 2; dx++) {
                    const int xi = x0 + dx;
                    if (xi < 0 || xi >= Wl) continue;
                    const float wx = dx ? wx1 : wx0;
                    acc += a * wx * wy * value[vbase + (st + yi * Wl + xi) * 256];
                }
            }
        }
    }
    outp[row * 256 + t] = rtf(acc);
}

// ---------------------------------------------------------------------------
// LayerNorm over C=256 of (A + B); optional rounded side copy
// ---------------------------------------------------------------------------
__global__ void ln_kernel(const float* __restrict__ A, const float* __restrict__ Bt,
                          const float* __restrict__ g, const float* __restrict__ be,
                          float* __restrict__ out, float* __restrict__ out_r) {
    const int row = blockIdx.x;
    const int t = threadIdx.x;
    const float v = A[row * 256 + t] + Bt[row * 256 + t];

    __shared__ float sh[8];
    __shared__ float sh2[8];

    float s = v;
#pragma unroll
    for (int o = 16; o > 0; o >>= 1) s += __shfl_xor_sync(0xffffffffu, s, o);
    if ((t & 31) == 0) sh[t >> 5] = s;
    __syncthreads();
    float mean = 0.f;
#pragma unroll
    for (int i = 0; i < 8; i++) mean += sh[i];
    mean *= (1.f / 256.f);

    const float d = v - mean;
    float s2 = d * d;
#pragma unroll
    for (int o = 16; o > 0; o >>= 1) s2 += __shfl_xor_sync(0xffffffffu, s2, o);
    if ((t & 31) == 0) sh2[t >> 5] = s2;
    __syncthreads();
    float var = 0.f;
#pragma unroll
    for (int i = 0; i < 8; i++) var += sh2[i];
    var *= (1.f / 256.f);

    const float o = d * rsqrtf(var + 1e-5f) * g[t] + be[t];
    out[row * 256 + t] = o;
    if (out_r) out_r[row * 256 + t] = rtf(o);
}

// ---------------------------------------------------------------------------
// Launch
// ---------------------------------------------------------------------------
extern "C" void kernel_launch(void* const* d_in, const int* in_sizes, int n_in,
                              void* d_out, int out_size) {
    const float* src  = (const float*)d_in[0];
    const float* pos  = (const float*)d_in[1];
    const float* refp = (const float*)d_in[2];
    const int*   shp  = (const int*)d_in[3];
    const int*   lst  = (const int*)d_in[4];
    const float* Wv   = (const float*)d_in[5];
    const float* bv   = (const float*)d_in[6];
    const float* Woff = (const float*)d_in[7];
    const float* boff = (const float*)d_in[8];
    const float* Waw  = (const float*)d_in[9];
    const float* baw  = (const float*)d_in[10];
    const float* Wo   = (const float*)d_in[11];
    const float* bo   = (const float*)d_in[12];
    const float* W1   = (const float*)d_in[13];
    const float* b1   = (const float*)d_in[14];
    const float* W2   = (const float*)d_in[15];
    const float* b2   = (const float*)d_in[16];
    const float* g1   = (const float*)d_in[17];
    const float* be1  = (const float*)d_in[18];
    const float* g2   = (const float*)d_in[19];
    const float* be2  = (const float*)d_in[20];

    const int M = in_sizes[0] / CDIM;   // 43520
    const int Lq = 21760;
    float* out = (float*)d_out;

    float *q, *srcr, *val, *offaw, *attn, *x, *xr, *hid, *f, *wt, *bcat;
    cudaGetSymbolAddress((void**)&q,     g_q);
    cudaGetSymbolAddress((void**)&srcr,  g_srcr);
    cudaGetSymbolAddress((void**)&val,   g_val);
    cudaGetSymbolAddress((void**)&offaw, g_offaw);
    cudaGetSymbolAddress((void**)&attn,  g_attn);
    cudaGetSymbolAddress((void**)&x,     g_x);
    cudaGetSymbolAddress((void**)&xr,    g_xr);
    cudaGetSymbolAddress((void**)&hid,   g_hid);
    cudaGetSymbolAddress((void**)&f,     g_f);
    cudaGetSymbolAddress((void**)&wt,    g_wt);
    cudaGetSymbolAddress((void**)&bcat,  g_bcat);

    cudaFuncSetAttribute(gemm_mma_kernel<false, false>,
                         cudaFuncAttributeMaxDynamicSharedMemorySize, GSMEM_BYTES);
    cudaFuncSetAttribute(gemm_mma_kernel<true, true>,
                         cudaFuncAttributeMaxDynamicSharedMemorySize, GSMEM_BYTES);

    // transpose + round weights to [N][K]; Woff rows then Waw rows are contiguous
    dim3 tb(32, 8);
    transpose_kernel<<<dim3(CDIM / 32, CDIM / 32), tb>>>(Wv,   wt + WT_WV,   CDIM, CDIM);
    transpose_kernel<<<dim3(CDIM / 32, CDIM / 32), tb>>>(Woff, wt + WT_WOFF, CDIM, CDIM);
    transpose_kernel<<<dim3(128 / 32,  CDIM / 32), tb>>>(Waw,  wt + WT_WAW,  CDIM, 128);
    transpose_kernel<<<dim3(CDIM / 32, CDIM / 32), tb>>>(Wo,   wt + WT_WO,   CDIM, CDIM);
    transpose_kernel<<<dim3(FDIM / 32, CDIM / 32), tb>>>(W1,   wt + WT_W1,   CDIM, FDIM);
    transpose_kernel<<<dim3(CDIM / 32, FDIM / 32), tb>>>(W2,   wt + WT_W2,   FDIM, CDIM);
    bcat_kernel<<<2, 256>>>(boff, baw, bcat);

    const int nElem = M * CDIM;
    addq_kernel<<<(nElem + 255) / 256, 256>>>(src, pos, q, srcr, nElem);

    dim3 blk(128);
    // val = src_r @ Wv + bv
    gemm_mma_kernel<false, false><<<dim3(CDIM / 128, M / 128), blk, GSMEM_BYTES>>>(
        srcr, wt + WT_WV, bv, val, M, CDIM, CDIM);
    // offaw = q @ [Woff|Waw] + [boff|baw]   (fused, N=384)
    gemm_mma_kernel<false, false><<<dim3(384 / 128, M / 128), blk, GSMEM_BYTES>>>(
        q, wt + WT_WOFF, bcat, offaw, M, 384, CDIM);
    // sampling (softmax fused), rounded fp32 out
    sample_kernel<<<M, 256>>>(val, offaw, refp, shp, lst, attn, Lq);
    // f = attn @ Wo + bo
    gemm_mma_kernel<false, false><<<dim3(CDIM / 128, M / 128), blk, GSMEM_BYTES>>>(
        attn, wt + WT_WO, bo, f, M, CDIM, CDIM);
    ln_kernel<<<M, 256>>>(src, f, g1, be1, x, xr);
    // hid (rounded, relu) = xr @ W1 + b1
    gemm_mma_kernel<true, true><<<dim3(FDIM / 128, M / 128), blk, GSMEM_BYTES>>>(
        xr, wt + WT_W1, b1, hid, M, FDIM, CDIM);
    // f = hid @ W2 + b2
    gemm_mma_kernel<false, false><<<dim3(CDIM / 128, M / 128), blk, GSMEM_BYTES>>>(
        hid, wt + WT_W2, b2, f, M, CDIM, FDIM);
    ln_kernel<<<M, 256>>>(x, f, g2, be2, out, nullptr);
}

// round 16
// speedup vs baseline: 1.5917x; 1.0164x over previous
#include <cuda_runtime.h>
#include <cstdint>
#include <math.h>

// ---------------------------------------------------------------------------
// Problem constants: B=2, Lq=21760, C=256, FD=1024, NH=8, d=32, NL=4, NP=4
// ---------------------------------------------------------------------------
#define MROWS 43520
#define CDIM  256
#define FDIM  1024

// Scratch (device globals)
__device__ float g_q    [MROWS * CDIM];   // rounded q
__device__ float g_srcr [MROWS * CDIM];   // rounded src
__device__ float g_val  [MROWS * CDIM];
__device__ float g_offaw[MROWS * 384];    // cols 0..255 offsets, 256..383 aw logits
__device__ float g_attn [MROWS * CDIM];   // rounded
__device__ float g_x    [MROWS * CDIM];
__device__ float g_xr   [MROWS * CDIM];   // rounded
__device__ float g_hid  [MROWS * FDIM];   // rounded
__device__ float g_f    [MROWS * CDIM];
__device__ float g_wt   [3 * 65536 + 32768 + 2 * 262144]; // rounded, [N][K]
__device__ float g_bcat [384];            // boff ++ baw

#define WT_WV   0
#define WT_WOFF 65536            // [384][256] combined: Woff rows 0..255, Waw rows 256..383
#define WT_WAW  131072
#define WT_WO   163840
#define WT_W1   229376
#define WT_W2   491520

// ---------------------------------------------------------------------------
// helpers
// ---------------------------------------------------------------------------
__device__ __forceinline__ uint32_t f2tf32(float v) {
    uint32_t o;
    asm("cvt.rna.tf32.f32 %0, %1;" : "=r"(o) : "f"(v));
    return o;
}
__device__ __forceinline__ float rtf(float v) { return __uint_as_float(f2tf32(v)); }

__device__ __forceinline__ void mma_tf32(float* d, const uint32_t* a, uint32_t b0, uint32_t b1) {
    asm volatile(
        "mma.sync.aligned.m16n8k8.row.col.f32.tf32.tf32.f32 "
        "{%0,%1,%2,%3}, {%4,%5,%6,%7}, {%8,%9}, {%0,%1,%2,%3};"
        : "+f"(d[0]), "+f"(d[1]), "+f"(d[2]), "+f"(d[3])
        : "r"(a[0]), "r"(a[1]), "r"(a[2]), "r"(a[3]), "r"(b0), "r"(b1));
}

__device__ __forceinline__ void ldsm4(uint32_t& r0, uint32_t& r1, uint32_t& r2, uint32_t& r3,
                                      uint32_t addr) {
    asm volatile("ldmatrix.sync.aligned.m8n8.x4.shared.b16 {%0,%1,%2,%3}, [%4];"
                 : "=r"(r0), "=r"(r1), "=r"(r2), "=r"(r3) : "r"(addr));
}

__device__ __forceinline__ uint32_t smem_u32(const void* p) {
    uint32_t a;
    asm("{ .reg .u64 t; cvta.to.shared.u64 t, %1; cvt.u32.u64 %0, t; }" : "=r"(a) : "l"(p));
    return a;
}
__device__ __forceinline__ void cp16(uint32_t dst, const void* src) {
    asm volatile("cp.async.ca.shared.global [%0], [%1], 16;" :: "r"(dst), "l"(src));
}
#define CP_COMMIT() asm volatile("cp.async.commit_group;" ::: "memory")
#define CP_WAIT1()  asm volatile("cp.async.wait_group 1;" ::: "memory")
#define CP_WAIT0()  asm volatile("cp.async.wait_group 0;" ::: "memory")

// ---------------------------------------------------------------------------
// Batched weight transpose + tf32 round: one launch for all 6 matrices.
// Wt[n*K+k] = round(W[k*N+n]), 32x32 tiles.
// ---------------------------------------------------------------------------
struct TransDesc { const float* W; float* Wt; int K; int N; int base; };
struct TransArgs { TransDesc d[6]; };

__global__ void transpose_all_kernel(TransArgs a) {
    __shared__ float t[32][33];
    const int bid = blockIdx.x;
    int m = 0;
#pragma unroll
    for (int i = 1; i < 6; i++)
        if (bid >= a.d[i].base) m = i;
    const TransDesc dd = a.d[m];
    const int local = bid - dd.base;
    const int tilesX = dd.N >> 5;
    const int n0 = (local % tilesX) * 32;
    const int k0 = (local / tilesX) * 32;
    const int tx = threadIdx.x, ty = threadIdx.y;
    for (int r = ty; r < 32; r += 8) t[r][tx] = dd.W[(long)(k0 + r) * dd.N + n0 + tx];
    __syncthreads();
    for (int r = ty; r < 32; r += 8) dd.Wt[(long)(n0 + r) * dd.K + k0 + tx] = rtf(t[tx][r]);
}

// concat biases: bcat = [boff(256), baw(128)]
__global__ void bcat_kernel(const float* __restrict__ boff, const float* __restrict__ baw,
                            float* __restrict__ bcat) {
    int i = threadIdx.x + blockIdx.x * blockDim.x;
    if (i < 256) bcat[i] = boff[i];
    else if (i < 384) bcat[i] = baw[i - 256];
}

// ---------------------------------------------------------------------------
// Tensor-core tf32 GEMM: C[M,N] = A[M,K] @ Bt[N,K]^T + bias.
// BM=BN=128, BK=32, 128 threads (4 warps, 2x2), warp tile 64x64.
// cp.async 2-stage pipeline + ldmatrix fragment loads.
// Smem pitch 36 u32 -> conflict-free LDSM row fetches.
// Requires M%128==0, N%128==0, K%32==0. Inputs pre-rounded to tf32.
// ---------------------------------------------------------------------------
#define GP 36
#define AMAT 4608              // 128*36 u32 per matrix
#define STAGE_U32 (2 * AMAT)   // A + B per stage
#define GSMEM_BYTES (2 * STAGE_U32 * 4)  // 73728

template <bool RELU, bool ROUND>
__global__ __launch_bounds__(128, 2)
void gemm_mma_kernel(const float* __restrict__ A, const float* __restrict__ Bt,
                     const float* __restrict__ bias, float* __restrict__ C,
                     int M, int N, int K) {
    extern __shared__ uint32_t sm[];

    const int tid = threadIdx.x;
    const int wid = tid >> 5;
    const int lid = tid & 31;
    const int row0 = blockIdx.y * 128;
    const int col0 = blockIdx.x * 128;
    const int wm = (wid & 1) * 64;
    const int wn = (wid >> 1) * 64;
    const int r = lid >> 2;          // 0..7
    const int c = lid & 3;           // 0..3

    // copy geometry: 8 slots/matrix, slot s -> row rbase+16s, fixed kq
    const int rbase = tid >> 3;          // 0..15
    const int kq    = (tid & 7) * 4;     // 0..28
    const float* Ag = A  + (long)(row0 + rbase) * K + kq;
    const float* Bg = Bt + (long)(col0 + rbase) * K + kq;
    const uint32_t smBase = smem_u32(sm);

    // ldmatrix per-lane word offsets (within stage)
    uint32_t aoff[4];
#pragma unroll
    for (int mt = 0; mt < 4; mt++)
        aoff[mt] = (uint32_t)((wm + mt * 16 + (lid & 15)) * GP + 4 * (lid >> 4));
    uint32_t boff4[4];
#pragma unroll
    for (int p = 0; p < 4; p++)
        boff4[p] = (uint32_t)(AMAT + (wn + p * 16 + (lid & 7) + 8 * (lid >> 4)) * GP
                              + 4 * ((lid >> 3) & 1));

    const int nk = K >> 5;

    float acc[4][8][4];
#pragma unroll
    for (int mt = 0; mt < 4; mt++)
#pragma unroll
        for (int nt = 0; nt < 8; nt++)
#pragma unroll
            for (int e = 0; e < 4; e++) acc[mt][nt][e] = 0.f;

    // prologue: stage 0, chunk 0
    {
        const uint32_t sA = smBase;
        const uint32_t sB = smBase + AMAT * 4;
#pragma unroll
        for (int s = 0; s < 8; s++) {
            const int row = rbase + 16 * s;
            const uint32_t so = (uint32_t)(row * GP + kq) * 4;
            cp16(sA + so, Ag + (long)(16 * s) * K);
            cp16(sB + so, Bg + (long)(16 * s) * K);
        }
        CP_COMMIT();
    }

    for (int i = 0; i < nk; i++) {
        const int cur = i & 1;
        if (i + 1 < nk) {
            const int nxt = cur ^ 1;
            const uint32_t sA = smBase + (uint32_t)nxt * STAGE_U32 * 4;
            const uint32_t sB = sA + AMAT * 4;
            const long ko = (long)(i + 1) * 32;
#pragma unroll
            for (int s = 0; s < 8; s++) {
                const int row = rbase + 16 * s;
                const uint32_t so = (uint32_t)(row * GP + kq) * 4;
                cp16(sA + so, Ag + (long)(16 * s) * K + ko);
                cp16(sB + so, Bg + (long)(16 * s) * K + ko);
            }
            CP_COMMIT();
            CP_WAIT1();
        } else {
            CP_WAIT0();
        }
        __syncthreads();

        const uint32_t stageB = smBase + (uint32_t)cur * STAGE_U32 * 4;

#pragma unroll
        for (int ks = 0; ks < 4; ks++) {
            const uint32_t kb4 = (uint32_t)(ks * 8) * 4;
            uint32_t a[4][4];
#pragma unroll
            for (int mt = 0; mt < 4; mt++)
                ldsm4(a[mt][0], a[mt][1], a[mt][2], a[mt][3], stageB + aoff[mt] * 4 + kb4);
            uint32_t b[8][2];
#pragma unroll
            for (int p = 0; p < 4; p++)
                ldsm4(b[2 * p][0], b[2 * p][1], b[2 * p + 1][0], b[2 * p + 1][1],
                      stageB + boff4[p] * 4 + kb4);
#pragma unroll
            for (int nt = 0; nt < 8; nt++)
#pragma unroll
                for (int mt = 0; mt < 4; mt++)
                    mma_tf32(acc[mt][nt], a[mt], b[nt][0], b[nt][1]);
        }
        __syncthreads();
    }

    // epilogue
    float2 bias2[8];
#pragma unroll
    for (int nt = 0; nt < 8; nt++)
        bias2[nt] = *(const float2*)&bias[col0 + wn + nt * 8 + 2 * c];

#pragma unroll
    for (int mt = 0; mt < 4; mt++) {
        const long gr0 = row0 + wm + mt * 16 + r;
        const long gr1 = gr0 + 8;
#pragma unroll
        for (int nt = 0; nt < 8; nt++) {
            const int gc = col0 + wn + nt * 8 + 2 * c;
            float2 v0, v1;
            v0.x = acc[mt][nt][0] + bias2[nt].x;
            v0.y = acc[mt][nt][1] + bias2[nt].y;
            v1.x = acc[mt][nt][2] + bias2[nt].x;
            v1.y = acc[mt][nt][3] + bias2[nt].y;
            if (RELU) {
                v0.x = fmaxf(v0.x, 0.f); v0.y = fmaxf(v0.y, 0.f);
                v1.x = fmaxf(v1.x, 0.f); v1.y = fmaxf(v1.y, 0.f);
            }
            if (ROUND) {
                v0.x = rtf(v0.x); v0.y = rtf(v0.y);
                v1.x = rtf(v1.x); v1.y = rtf(v1.y);
            }
            *(float2*)&C[gr0 * N + gc] = v0;
            *(float2*)&C[gr1 * N + gc] = v1;
        }
    }
}

// ---------------------------------------------------------------------------
// q = round(src + pos); src_r = round(src)
// ---------------------------------------------------------------------------
__global__ void addq_kernel(const float* __restrict__ a, const float* __restrict__ b,
                            float* __restrict__ q, float* __restrict__ sr, int n) {
    int i = blockIdx.x * blockDim.x + threadIdx.x;
    if (i < n) {
        float s = a[i];
        q[i] = rtf(s + b[i]);
        sr[i] = rtf(s);
    }
}

// ---------------------------------------------------------------------------
// Deformable sampling with fused softmax.
// offaw: [M][384] — cols 0..255 offsets, 256..383 aw logits.
// One block per token (256 threads = 8 heads x 32 ch).
// ---------------------------------------------------------------------------
__global__ void sample_kernel(const float* __restrict__ value, const float* __restrict__ offaw,
                              const float* __restrict__ refp,
                              const int* __restrict__ shapes, const int* __restrict__ lstart,
                              float* __restrict__ outp, int Lq) {
    const int row = blockIdx.x;
    const int t = threadIdx.x;
    const int b = row / Lq;

    __shared__ float s_off[256];
    __shared__ float s_aw[128];
    __shared__ float s_ref[8];
    __shared__ int   s_hw[8];
    __shared__ int   s_st[4];

    s_off[t] = offaw[(long)row * 384 + t];
    if (t < 8)   s_ref[t] = refp[row * 8 + t];
    if (t < 8)   s_hw[t] = shapes[t];
    if (t < 4)   s_st[t] = lstart[t];
    if (t < 128) {
        const float v = offaw[(long)row * 384 + 256 + t];
        float m = v;
#pragma unroll
        for (int o = 8; o > 0; o >>= 1) m = fmaxf(m, __shfl_xor_sync(0xffffffffu, m, o, 16));
        const float e = expf(v - m);
        float s = e;
#pragma unroll
        for (int o = 8; o > 0; o >>= 1) s += __shfl_xor_sync(0xffffffffu, s, o, 16);
        s_aw[t] = e / s;
    }
    __syncthreads();

    const int h = t >> 5;
    const int j = t & 31;
    const int vbase = b * Lq * 256 + h * 32 + j;

    float acc = 0.f;
#pragma unroll
    for (int l = 0; l < 4; l++) {
        const int Hl = s_hw[l * 2], Wl = s_hw[l * 2 + 1];
        const int st = s_st[l];
        const float rx = s_ref[l * 2], ry = s_ref[l * 2 + 1];
        const float fW = (float)Wl, fH = (float)Hl;
#pragma unroll
        for (int p = 0; p < 4; p++) {
            const int oi = (h * 16 + l * 4 + p) * 2;
            const float px = (rx + s_off[oi] / fW) * fW - 0.5f;
            const float py = (ry + s_off[oi + 1] / fH) * fH - 0.5f;
            const float fx = floorf(px), fy = floorf(py);
            const int x0 = (int)fx, y0 = (int)fy;
            const float wx1 = px - fx, wy1 = py - fy;
            const float wx0 = 1.f - wx1, wy0 = 1.f - wy1;
            const float a = s_aw[h * 16 + l * 4 + p];

#pragma unroll
            for (int dy = 0; dy < 2; dy++) {
                const int yi = y0 + dy;
                if (yi < 0 || yi >= Hl) continue;
                const float wy = dy ? wy1 : wy0;
#pragma unroll
                for (int dx = 0; dx < 2; dx++) {
                    const int xi = x0 + dx;
                    if (xi < 0 || xi >= Wl) continue;
                    const float wx = dx ? wx1 : wx0;
                    acc += a * wx * wy * value[vbase + (st + yi * Wl + xi) * 256];
                }
            }
        }
    }
    outp[row * 256 + t] = rtf(acc);
}

// ---------------------------------------------------------------------------
// LayerNorm over C=256 of (A + B); optional rounded side copy
// ---------------------------------------------------------------------------
__global__ void ln_kernel(const float* __restrict__ A, const float* __restrict__ Bt,
                          const float* __restrict__ g, const float* __restrict__ be,
                          float* __restrict__ out, float* __restrict__ out_r) {
    const int row = blockIdx.x;
    const int t = threadIdx.x;
    const float v = A[row * 256 + t] + Bt[row * 256 + t];

    __shared__ float sh[8];
    __shared__ float sh2[8];

    float s = v;
#pragma unroll
    for (int o = 16; o > 0; o >>= 1) s += __shfl_xor_sync(0xffffffffu, s, o);
    if ((t & 31) == 0) sh[t >> 5] = s;
    __syncthreads();
    float mean = 0.f;
#pragma unroll
    for (int i = 0; i < 8; i++) mean += sh[i];
    mean *= (1.f / 256.f);

    const float d = v - mean;
    float s2 = d * d;
#pragma unroll
    for (int o = 16; o > 0; o >>= 1) s2 += __shfl_xor_sync(0xffffffffu, s2, o);
    if ((t & 31) == 0) sh2[t >> 5] = s2;
    __syncthreads();
    float var = 0.f;
#pragma unroll
    for (int i = 0; i < 8; i++) var += sh2[i];
    var *= (1.f / 256.f);

    const float o = d * rsqrtf(var + 1e-5f) * g[t] + be[t];
    out[row * 256 + t] = o;
    if (out_r) out_r[row * 256 + t] = rtf(o);
}

// ---------------------------------------------------------------------------
// Launch
// ---------------------------------------------------------------------------
extern "C" void kernel_launch(void* const* d_in, const int* in_sizes, int n_in,
                              void* d_out, int out_size) {
    const float* src  = (const float*)d_in[0];
    const float* pos  = (const float*)d_in[1];
    const float* refp = (const float*)d_in[2];
    const int*   shp  = (const int*)d_in[3];
    const int*   lst  = (const int*)d_in[4];
    const float* Wv   = (const float*)d_in[5];
    const float* bv   = (const float*)d_in[6];
    const float* Woff = (const float*)d_in[7];
    const float* boff = (const float*)d_in[8];
    const float* Waw  = (const float*)d_in[9];
    const float* baw  = (const float*)d_in[10];
    const float* Wo   = (const float*)d_in[11];
    const float* bo   = (const float*)d_in[12];
    const float* W1   = (const float*)d_in[13];
    const float* b1   = (const float*)d_in[14];
    const float* W2   = (const float*)d_in[15];
    const float* b2   = (const float*)d_in[16];
    const float* g1   = (const float*)d_in[17];
    const float* be1  = (const float*)d_in[18];
    const float* g2   = (const float*)d_in[19];
    const float* be2  = (const float*)d_in[20];

    const int M = in_sizes[0] / CDIM;   // 43520
    const int Lq = 21760;
    float* out = (float*)d_out;

    float *q, *srcr, *val, *offaw, *attn, *x, *xr, *hid, *f, *wt, *bcat;
    cudaGetSymbolAddress((void**)&q,     g_q);
    cudaGetSymbolAddress((void**)&srcr,  g_srcr);
    cudaGetSymbolAddress((void**)&val,   g_val);
    cudaGetSymbolAddress((void**)&offaw, g_offaw);
    cudaGetSymbolAddress((void**)&attn,  g_attn);
    cudaGetSymbolAddress((void**)&x,     g_x);
    cudaGetSymbolAddress((void**)&xr,    g_xr);
    cudaGetSymbolAddress((void**)&hid,   g_hid);
    cudaGetSymbolAddress((void**)&f,     g_f);
    cudaGetSymbolAddress((void**)&wt,    g_wt);
    cudaGetSymbolAddress((void**)&bcat,  g_bcat);

    cudaFuncSetAttribute(gemm_mma_kernel<false, false>,
                         cudaFuncAttributeMaxDynamicSharedMemorySize, GSMEM_BYTES);
    cudaFuncSetAttribute(gemm_mma_kernel<true, true>,
                         cudaFuncAttributeMaxDynamicSharedMemorySize, GSMEM_BYTES);

    // one batched transpose for all 6 weight matrices
    TransArgs ta;
    ta.d[0] = {Wv,   wt + WT_WV,   CDIM, CDIM, 0};
    ta.d[1] = {Woff, wt + WT_WOFF, CDIM, CDIM, 64};
    ta.d[2] = {Waw,  wt + WT_WAW,  CDIM, 128,  128};
    ta.d[3] = {Wo,   wt + WT_WO,   CDIM, CDIM, 160};
    ta.d[4] = {W1,   wt + WT_W1,   CDIM, FDIM, 224};
    ta.d[5] = {W2,   wt + WT_W2,   FDIM, CDIM, 480};
    dim3 tb(32, 8);
    transpose_all_kernel<<<736, tb>>>(ta);
    bcat_kernel<<<2, 256>>>(boff, baw, bcat);

    const int nElem = M * CDIM;
    addq_kernel<<<(nElem + 255) / 256, 256>>>(src, pos, q, srcr, nElem);

    dim3 blk(128);
    // val = src_r @ Wv + bv
    gemm_mma_kernel<false, false><<<dim3(CDIM / 128, M / 128), blk, GSMEM_BYTES>>>(
        srcr, wt + WT_WV, bv, val, M, CDIM, CDIM);
    // offaw = q @ [Woff|Waw] + [boff|baw]   (fused, N=384)
    gemm_mma_kernel<false, false><<<dim3(384 / 128, M / 128), blk, GSMEM_BYTES>>>(
        q, wt + WT_WOFF, bcat, offaw, M, 384, CDIM);
    // sampling (softmax fused), rounded fp32 out — launch index 5, profiled by ncu
    sample_kernel<<<M, 256>>>(val, offaw, refp, shp, lst, attn, Lq);
    // f = attn @ Wo + bo
    gemm_mma_kernel<false, false><<<dim3(CDIM / 128, M / 128), blk, GSMEM_BYTES>>>(
        attn, wt + WT_WO, bo, f, M, CDIM, CDIM);
    ln_kernel<<<M, 256>>>(src, f, g1, be1, x, xr);
    // hid (rounded, relu) = xr @ W1 + b1
    gemm_mma_kernel<true, true><<<dim3(FDIM / 128, M / 128), blk, GSMEM_BYTES>>>(
        xr, wt + WT_W1, b1, hid, M, FDIM, CDIM);
    // f = hid @ W2 + b2
    gemm_mma_kernel<false, false><<<dim3(CDIM / 128, M / 128), blk, GSMEM_BYTES>>>(
        hid, wt + WT_W2, b2, f, M, CDIM, FDIM);
    ln_kernel<<<M, 256>>>(x, f, g2, be2, out, nullptr);
}